// round 4
// baseline (speedup 1.0000x reference)
#include <cuda_runtime.h>
#include <math.h>

#define BATCH 1024
#define NIN   512
#define NHID  256

// ---------------------------------------------------------------------------
// Device-global scratch (no allocation allowed anywhere).
// ---------------------------------------------------------------------------
__device__ unsigned g_mT1[16 * NHID];        // transposed bitmask [w][node], layer1
__device__ unsigned g_mT2[8 * NIN];          // transposed bitmask [w][node], layer2
__device__ float    g_h[BATCH * NHID];       // layer-1 output, row-major [b][h]

// ---------------------------------------------------------------------------
// Gumbel hard-select: forward value is exactly one-hot of argmax(logits + g).
// ---------------------------------------------------------------------------
__device__ __forceinline__ float gumbel_f(float u) {
    u = fminf(fmaxf(u, 1e-10f), 1.0f);
    return -logf(-logf(u));
}

// Mask dtype detection (bool 1B / int32 / float32) — probe 64 words.
__device__ int detect_mode(const void* p) {
    const unsigned* pw = (const unsigned*)p;
    bool i32ok = true, f32ok = true;
    #pragma unroll 8
    for (int g = 0; g < 64; g++) {
        unsigned v = pw[g];
        i32ok = i32ok && (v == 0u || v == 1u);
        f32ok = f32ok && (v == 0u || v == 0x3F800000u);
    }
    return i32ok ? 2 : (f32ok ? 3 : 1);
}

__device__ __forceinline__ bool mask_at(const void* p, int mode, int e) {
    if (mode == 2) return ((const int*)p)[e] != 0;
    if (mode == 3) return ((const float*)p)[e] != 0.0f;
    return ((const unsigned char*)p)[e] != 0;
}

// Transposed bit-packed masks: g_mT[w][node]. One warp per node; ballot packs.
__global__ void prep_masks_kernel(const void* __restrict__ m1,
                                  const void* __restrict__ m2) {
    __shared__ int modes[2];
    if (threadIdx.x == 0) modes[0] = detect_mode(m1);
    if (threadIdx.x == 32) modes[1] = detect_mode(m2);
    __syncthreads();
    int gw   = (blockIdx.x * blockDim.x + threadIdx.x) >> 5;
    int lane = threadIdx.x & 31;
    if (gw < NHID) {
        int node = gw, mode = modes[0];
        #pragma unroll
        for (int w = 0; w < 16; w++) {
            bool b = mask_at(m1, mode, node * NIN + w * 32 + lane);
            unsigned bits = __ballot_sync(0xffffffffu, b);
            if (lane == 0) g_mT1[w * NHID + node] = bits;
        }
    } else if (gw < NHID + NIN) {
        int node = gw - NHID, mode = modes[1];
        #pragma unroll
        for (int w = 0; w < 8; w++) {
            bool b = mask_at(m2, mode, node * NHID + w * 32 + lane);
            unsigned bits = __ballot_sync(0xffffffffu, b);
            if (lane == 0) g_mT2[w * NIN + node] = bits;
        }
    }
}

// ---------------------------------------------------------------------------
// Warp bitonic sort of 32*R u32 keys, ascending. Element i = lane*R + r.
// ---------------------------------------------------------------------------
template<int R, int J>
__device__ __forceinline__ void inreg_pass(unsigned* key, int lane, int k) {
    if (2 * J > k) return;
    #pragma unroll
    for (int r = 0; r < R; r++) {
        if ((r & J) == 0) {
            bool asc = (((unsigned)(lane * R + r) & (unsigned)k) == 0);
            unsigned a = key[r], b = key[r + J];
            unsigned mn = a < b ? a : b;
            unsigned mx = a < b ? b : a;
            key[r]     = asc ? mn : mx;
            key[r + J] = asc ? mx : mn;
        }
    }
}

template<int R>
__device__ __forceinline__ void bitonic_sort_warp(unsigned* key) {
    const int lane = threadIdx.x & 31;
    const int N = 32 * R;
    for (int k = 2; k <= N; k <<= 1) {
        for (int m = (k >> 1) / R; m >= 1; m >>= 1) {
            #pragma unroll
            for (int r = 0; r < R; r++) {
                unsigned a = key[r];
                unsigned b = __shfl_xor_sync(0xffffffffu, a, m);
                bool asc   = (((unsigned)(lane * R + r) & (unsigned)k) == 0);
                bool lower = ((lane & m) == 0);
                unsigned mn = a < b ? a : b;
                unsigned mx = a < b ? b : a;
                key[r] = (lower == asc) ? mn : mx;
            }
        }
        if (R >= 16) inreg_pass<R, 8>(key, lane, k);
        if (R >= 8)  inreg_pass<R, 4>(key, lane, k);
        inreg_pass<R, 2>(key, lane, k);
        inreg_pass<R, 1>(key, lane, k);
    }
}

// ---------------------------------------------------------------------------
// Fused sort+walk kernel. Block = 4 batch rows x ALL nodes, 256 threads.
// Warps 0-3: load their row from global, bitonic-sort it, publish sorted keys.
// Warps 4-7: concurrently stage masks/values/sel into smem.
// Then every thread walks 4 row-chains (interleaved for MLP) per node it owns,
// from the sel-dependent end of the sorted list to the first active element.
// ---------------------------------------------------------------------------
template<int N, int NNODES, int LAYER>
__global__ void __launch_bounds__(256) fused_kernel(const float* __restrict__ in_arg,
                                                    float* __restrict__ out_arg,
                                                    const float* __restrict__ logits,
                                                    const float* __restrict__ uu) {
    constexpr int R   = N / 32;      // keys per lane in the sort
    constexpr int MW  = N / 32;      // mask words per node
    constexpr int RPB = 4;           // rows per block
    __shared__ __align__(16) unsigned      s_keys[RPB][N];
    __shared__ __align__(16) float         s_vals[RPB][N];
    __shared__ __align__(16) unsigned      s_mask[MW * NNODES];
    __shared__ unsigned char               s_sel[NNODES];

    const int tid  = threadIdx.x;
    const int warp = tid >> 5;
    const int lane = tid & 31;
    const int r0   = blockIdx.x * RPB;

    const float*    in = (LAYER == 1) ? in_arg : g_h;
    float*          op = (LAYER == 1) ? g_h    : out_arg;
    const unsigned* mg = (LAYER == 1) ? g_mT1  : g_mT2;

    if (warp < RPB) {
        // ---- sort my row (load straight from global: coalesced 4×float4/lane)
        const float* src = in + (size_t)(r0 + warp) * N + lane * R;
        unsigned key[R];
        #pragma unroll
        for (int rr = 0; rr < R; rr += 4) {
            float4 v = *(const float4*)(src + rr);
            float vv[4] = {v.x, v.y, v.z, v.w};
            #pragma unroll
            for (int q = 0; q < 4; q++) {
                int c = lane * R + rr + q;
                key[rr + q] = (__float_as_uint(vv[q]) & ~(unsigned)(N - 1)) | (unsigned)c;
            }
        }
        bitonic_sort_warp<R>(key);
        #pragma unroll
        for (int rr = 0; rr < R; rr += 4) {
            uint4 o; o.x = key[rr]; o.y = key[rr + 1]; o.z = key[rr + 2]; o.w = key[rr + 3];
            *(uint4*)(&s_keys[warp][lane * R + rr]) = o;
        }
    } else {
        const int t2 = tid - 128;   // 0..127
        // ---- masks (direct copy: g_mT layout already [w][node] over all nodes)
        const uint4* mg4 = (const uint4*)mg;
        uint4* sm4 = (uint4*)s_mask;
        #pragma unroll
        for (int i = t2; i < (MW * NNODES) / 4; i += 128) sm4[i] = mg4[i];
        // ---- exact values for the 4 rows (contiguous, vectorized)
        const float4* in4 = (const float4*)(in + (size_t)r0 * N);
        float4* sv4 = (float4*)&s_vals[0][0];
        #pragma unroll
        for (int i = t2; i < (RPB * N) / 4; i += 128) sv4[i] = in4[i];
        // ---- sel per node (recomputed per block: cheaper than a launch)
        for (int n = t2; n < NNODES; n += 128) {
            float z0 = logits[2 * n]     + gumbel_f(uu[2 * n]);
            float z1 = logits[2 * n + 1] + gumbel_f(uu[2 * n + 1]);
            s_sel[n] = (z1 > z0) ? 1 : 0;
        }
    }
    __syncthreads();

    // ---- walks: each thread owns NNODES/256 nodes, 4 interleaved row-chains each
    #pragma unroll
    for (int np = 0; np < NNODES / 256; np++) {
        const int node = np * 256 + tid;
        const int sel  = s_sel[node];
        const unsigned posm = sel ? (unsigned)(N - 1) : 0u;   // max: walk descending
        const float idv = sel ? 0.0f : 1.0f;                  // empty-mask identity
        float v[RPB]; bool f[RPB];
        #pragma unroll
        for (int r = 0; r < RPB; r++) { v[r] = idv; f[r] = false; }

        for (int t = 0; t < N; t++) {
            const unsigned p = (unsigned)t ^ posm;
            bool alldone = true;
            #pragma unroll
            for (int r = 0; r < RPB; r++) {
                if (!f[r]) {
                    unsigned kk = s_keys[r][p];                 // broadcast LDS
                    int idx = (int)(kk & (unsigned)(N - 1));
                    if ((s_mask[(idx >> 5) * NNODES + node] >> (idx & 31)) & 1u) {
                        v[r] = s_vals[r][idx]; f[r] = true;
                    }
                }
                alldone &= f[r];
            }
            if (alldone) break;
        }
        #pragma unroll
        for (int r = 0; r < RPB; r++)
            op[(size_t)(r0 + r) * NNODES + node] = fmaxf(v[r], 0.0f);
    }
}

// ---------------------------------------------------------------------------
// kernel_launch: masks -> fused layer1 -> fused layer2. Three launches.
// ---------------------------------------------------------------------------
extern "C" void kernel_launch(void* const* d_in, const int* in_sizes, int n_in,
                              void* d_out, int out_size) {
    const float* x       = (const float*)d_in[0];
    const float* logits1 = (const float*)d_in[1];
    const float* u1      = (const float*)d_in[2];
    const float* logits2 = (const float*)d_in[3];
    const float* u2      = (const float*)d_in[4];
    const void*  mask1   = d_in[5];
    const void*  mask2   = d_in[6];
    float* out = (float*)d_out;
    (void)in_sizes; (void)n_in; (void)out_size;

    prep_masks_kernel<<<96, 256>>>(mask1, mask2);
    fused_kernel<NIN,  NHID, 1><<<BATCH / 4, 256>>>(x, nullptr, logits1, u1);
    fused_kernel<NHID, NIN,  2><<<BATCH / 4, 256>>>(nullptr, out, logits2, u2);
}

// round 5
// speedup vs baseline: 1.0087x; 1.0087x over previous
#include <cuda_runtime.h>
#include <math.h>

#define BATCH 1024
#define NIN   512
#define NHID  256

// ---------------------------------------------------------------------------
// Device-global scratch (no allocation allowed anywhere).
// ---------------------------------------------------------------------------
__device__ unsigned g_mT1[16 * NHID];        // transposed bitmask [w][node], layer1
__device__ unsigned g_mT2[8 * NIN];          // transposed bitmask [w][node], layer2
__device__ float    g_h[BATCH * NHID];       // layer-1 output, row-major [b][h]

// ---------------------------------------------------------------------------
// Gumbel hard-select: forward value is exactly one-hot of argmax(logits + g).
// ---------------------------------------------------------------------------
__device__ __forceinline__ float gumbel_f(float u) {
    u = fminf(fmaxf(u, 1e-10f), 1.0f);
    return -logf(-logf(u));
}

// Mask dtype detection (bool 1B / int32 / float32) — probe 64 words.
__device__ int detect_mode(const void* p) {
    const unsigned* pw = (const unsigned*)p;
    bool i32ok = true, f32ok = true;
    #pragma unroll 8
    for (int g = 0; g < 64; g++) {
        unsigned v = pw[g];
        i32ok = i32ok && (v == 0u || v == 1u);
        f32ok = f32ok && (v == 0u || v == 0x3F800000u);
    }
    return i32ok ? 2 : (f32ok ? 3 : 1);
}

__device__ __forceinline__ bool mask_at(const void* p, int mode, int e) {
    if (mode == 2) return ((const int*)p)[e] != 0;
    if (mode == 3) return ((const float*)p)[e] != 0.0f;
    return ((const unsigned char*)p)[e] != 0;
}

// ---------------------------------------------------------------------------
// Transposed bit-packed masks, one WARP per output word: lane loads one mask
// element (coalesced 128B), ballot packs, lane 0 stores. 8192 warps total —
// all DRAM latency hidden by parallelism.
// ---------------------------------------------------------------------------
__global__ void __launch_bounds__(256) prep_masks_kernel(const void* __restrict__ m1,
                                                         const void* __restrict__ m2) {
    __shared__ int modes[2];
    if (threadIdx.x == 0)  modes[0] = detect_mode(m1);
    if (threadIdx.x == 32) modes[1] = detect_mode(m2);
    __syncthreads();
    const int gw   = (blockIdx.x * 256 + threadIdx.x) >> 5;   // global warp id
    const int lane = threadIdx.x & 31;
    const int W1 = NHID * 16;   // 4096 words
    if (gw < W1) {
        int node = gw >> 4, w = gw & 15;
        bool b = mask_at(m1, modes[0], node * NIN + w * 32 + lane);
        unsigned bits = __ballot_sync(0xffffffffu, b);
        if (lane == 0) g_mT1[w * NHID + node] = bits;
    } else {
        int g2 = gw - W1;                // 0..4095
        int node = g2 >> 3, w = g2 & 7;
        bool b = mask_at(m2, modes[1], node * NHID + w * 32 + lane);
        unsigned bits = __ballot_sync(0xffffffffu, b);
        if (lane == 0) g_mT2[w * NIN + node] = bits;
    }
}

// ---------------------------------------------------------------------------
// Warp bitonic sort of 32*R u32 keys, ascending. Element i = lane*R + r.
// ---------------------------------------------------------------------------
template<int R, int J>
__device__ __forceinline__ void inreg_pass(unsigned* key, int lane, int k) {
    if (2 * J > k) return;
    #pragma unroll
    for (int r = 0; r < R; r++) {
        if ((r & J) == 0) {
            bool asc = (((unsigned)(lane * R + r) & (unsigned)k) == 0);
            unsigned a = key[r], b = key[r + J];
            unsigned mn = a < b ? a : b;
            unsigned mx = a < b ? b : a;
            key[r]     = asc ? mn : mx;
            key[r + J] = asc ? mx : mn;
        }
    }
}

template<int R>
__device__ __forceinline__ void bitonic_sort_warp(unsigned* key) {
    const int lane = threadIdx.x & 31;
    const int N = 32 * R;
    for (int k = 2; k <= N; k <<= 1) {
        for (int m = (k >> 1) / R; m >= 1; m >>= 1) {
            #pragma unroll
            for (int r = 0; r < R; r++) {
                unsigned a = key[r];
                unsigned b = __shfl_xor_sync(0xffffffffu, a, m);
                bool asc   = (((unsigned)(lane * R + r) & (unsigned)k) == 0);
                bool lower = ((lane & m) == 0);
                unsigned mn = a < b ? a : b;
                unsigned mx = a < b ? b : a;
                key[r] = (lower == asc) ? mn : mx;
            }
        }
        if (R >= 16) inreg_pass<R, 8>(key, lane, k);
        if (R >= 8)  inreg_pass<R, 4>(key, lane, k);
        inreg_pass<R, 2>(key, lane, k);
        inreg_pass<R, 1>(key, lane, k);
    }
}

// ---------------------------------------------------------------------------
// Fused sort+walk kernel. Block = 4 batch rows x ALL nodes, 256 threads.
// Warps 0-3: load their row from global, bitonic-sort it, publish sorted keys.
// Warps 4-7: concurrently stage masks/values/sel into smem.
// Walk: each thread owns NPT nodes and walks ALL its RPB*NPT chains in one
// interleaved loop (max memory-level parallelism on the LDS chains).
// ---------------------------------------------------------------------------
template<int N, int NNODES, int LAYER>
__global__ void __launch_bounds__(256) fused_kernel(const float* __restrict__ in_arg,
                                                    float* __restrict__ out_arg,
                                                    const float* __restrict__ logits,
                                                    const float* __restrict__ uu) {
    constexpr int R   = N / 32;      // keys per lane in the sort
    constexpr int MW  = N / 32;      // mask words per node
    constexpr int RPB = 4;           // rows per block
    constexpr int NPT = NNODES / 256;// nodes per thread (1 or 2)
    __shared__ __align__(16) unsigned      s_keys[RPB][N];
    __shared__ __align__(16) float         s_vals[RPB][N];
    __shared__ __align__(16) unsigned      s_mask[MW * NNODES];
    __shared__ unsigned char               s_sel[NNODES];

    const int tid  = threadIdx.x;
    const int warp = tid >> 5;
    const int lane = tid & 31;
    const int r0   = blockIdx.x * RPB;

    const float*    in = (LAYER == 1) ? in_arg : g_h;
    float*          op = (LAYER == 1) ? g_h    : out_arg;
    const unsigned* mg = (LAYER == 1) ? g_mT1  : g_mT2;

    if (warp < RPB) {
        // ---- sort my row (load straight from global: coalesced 4×float4/lane)
        const float* src = in + (size_t)(r0 + warp) * N + lane * R;
        unsigned key[R];
        #pragma unroll
        for (int rr = 0; rr < R; rr += 4) {
            float4 v = *(const float4*)(src + rr);
            float vv[4] = {v.x, v.y, v.z, v.w};
            #pragma unroll
            for (int q = 0; q < 4; q++) {
                int c = lane * R + rr + q;
                key[rr + q] = (__float_as_uint(vv[q]) & ~(unsigned)(N - 1)) | (unsigned)c;
            }
        }
        bitonic_sort_warp<R>(key);
        #pragma unroll
        for (int rr = 0; rr < R; rr += 4) {
            uint4 o; o.x = key[rr]; o.y = key[rr + 1]; o.z = key[rr + 2]; o.w = key[rr + 3];
            *(uint4*)(&s_keys[warp][lane * R + rr]) = o;
        }
    } else {
        const int t2 = tid - 128;   // 0..127
        // ---- masks (direct copy: g_mT layout already [w][node] over all nodes)
        const uint4* mg4 = (const uint4*)mg;
        uint4* sm4 = (uint4*)s_mask;
        #pragma unroll
        for (int i = t2; i < (MW * NNODES) / 4; i += 128) sm4[i] = mg4[i];
        // ---- exact values for the 4 rows (contiguous, vectorized)
        const float4* in4 = (const float4*)(in + (size_t)r0 * N);
        float4* sv4 = (float4*)&s_vals[0][0];
        #pragma unroll
        for (int i = t2; i < (RPB * N) / 4; i += 128) sv4[i] = in4[i];
        // ---- sel per node (recomputed per block: cheaper than a launch)
        for (int n = t2; n < NNODES; n += 128) {
            float z0 = logits[2 * n]     + gumbel_f(uu[2 * n]);
            float z1 = logits[2 * n + 1] + gumbel_f(uu[2 * n + 1]);
            s_sel[n] = (z1 > z0) ? 1 : 0;
        }
    }
    __syncthreads();

    // ---- walks: NPT nodes/thread, all RPB*NPT chains interleaved in one loop
    unsigned posm[NPT];
    float    idv [NPT];
    float    v[NPT][RPB];
    bool     f[NPT][RPB];
    #pragma unroll
    for (int np = 0; np < NPT; np++) {
        const int node = np * 256 + tid;
        const int sel  = s_sel[node];
        posm[np] = sel ? (unsigned)(N - 1) : 0u;   // max: walk descending
        idv [np] = sel ? 0.0f : 1.0f;              // empty-mask identity
        #pragma unroll
        for (int r = 0; r < RPB; r++) { v[np][r] = idv[np]; f[np][r] = false; }
    }

    for (int t = 0; t < N; t++) {
        bool alldone = true;
        #pragma unroll
        for (int np = 0; np < NPT; np++) {
            const int node = np * 256 + tid;
            const unsigned p = (unsigned)t ^ posm[np];
            #pragma unroll
            for (int r = 0; r < RPB; r++) {
                if (!f[np][r]) {
                    unsigned kk = s_keys[r][p];                 // broadcast LDS
                    int idx = (int)(kk & (unsigned)(N - 1));
                    if ((s_mask[(idx >> 5) * NNODES + node] >> (idx & 31)) & 1u) {
                        v[np][r] = s_vals[r][idx]; f[np][r] = true;
                    }
                }
                alldone &= f[np][r];
            }
        }
        if (alldone) break;
    }
    #pragma unroll
    for (int np = 0; np < NPT; np++) {
        const int node = np * 256 + tid;
        #pragma unroll
        for (int r = 0; r < RPB; r++)
            op[(size_t)(r0 + r) * NNODES + node] = fmaxf(v[np][r], 0.0f);
    }
}

// ---------------------------------------------------------------------------
// kernel_launch: masks -> fused layer1 -> fused layer2. Three launches.
// ---------------------------------------------------------------------------
extern "C" void kernel_launch(void* const* d_in, const int* in_sizes, int n_in,
                              void* d_out, int out_size) {
    const float* x       = (const float*)d_in[0];
    const float* logits1 = (const float*)d_in[1];
    const float* u1      = (const float*)d_in[2];
    const float* logits2 = (const float*)d_in[3];
    const float* u2      = (const float*)d_in[4];
    const void*  mask1   = d_in[5];
    const void*  mask2   = d_in[6];
    float* out = (float*)d_out;
    (void)in_sizes; (void)n_in; (void)out_size;

    prep_masks_kernel<<<1024, 256>>>(mask1, mask2);
    fused_kernel<NIN,  NHID, 1><<<BATCH / 4, 256>>>(x, nullptr, logits1, u1);
    fused_kernel<NHID, NIN,  2><<<BATCH / 4, 256>>>(nullptr, out, logits2, u2);
}

// round 6
// speedup vs baseline: 1.2272x; 1.2166x over previous
#include <cuda_runtime.h>
#include <math.h>

#define BATCH 1024
#define NIN   512
#define NHID  256

// ---------------------------------------------------------------------------
// Device-global scratch (no allocation allowed anywhere).
// ---------------------------------------------------------------------------
__device__ unsigned g_mT1[16 * NHID];        // transposed bitmask [w][node], layer1
__device__ unsigned g_mT2[8 * NIN];          // transposed bitmask [w][node], layer2

// ---------------------------------------------------------------------------
// Gumbel hard-select: forward value is exactly one-hot of argmax(logits + g).
// ---------------------------------------------------------------------------
__device__ __forceinline__ float gumbel_f(float u) {
    u = fminf(fmaxf(u, 1e-10f), 1.0f);
    return -logf(-logf(u));
}

// Per-warp mask dtype detection: 2 lane-parallel loads + ballots. No barrier,
// no serial chain. (bool 1B -> 1, int32 -> 2, float32 -> 3)
__device__ __forceinline__ int warp_detect(const void* p, int lane) {
    const unsigned* pw = (const unsigned*)p;
    unsigned a = pw[lane], b = pw[lane + 32];
    bool i32 = (a <= 1u) && (b <= 1u);
    bool f32 = (a == 0u || a == 0x3F800000u) && (b == 0u || b == 0x3F800000u);
    i32 = __all_sync(0xffffffffu, i32);
    f32 = __all_sync(0xffffffffu, f32);
    return i32 ? 2 : (f32 ? 3 : 1);
}

__device__ __forceinline__ bool mask_at(const void* p, int mode, int e) {
    if (mode == 2) return ((const int*)p)[e] != 0;
    if (mode == 3) return ((const float*)p)[e] != 0.0f;
    return ((const unsigned char*)p)[e] != 0;
}

// ---------------------------------------------------------------------------
// Transposed bit-packed masks. One warp packs 4 words (4 independent coalesced
// 128B loads -> MLP). 2048 warps; detection amortized per warp.
// ---------------------------------------------------------------------------
__global__ void __launch_bounds__(256) prep_masks_kernel(const void* __restrict__ m1,
                                                         const void* __restrict__ m2) {
    const int gw   = (blockIdx.x * 256 + threadIdx.x) >> 5;   // 0..2047
    const int lane = threadIdx.x & 31;
    if (gw < 1024) {                       // mask1: words 0..4095
        const int mode = warp_detect(m1, lane);
        #pragma unroll
        for (int q = 0; q < 4; q++) {
            int wi = gw * 4 + q;
            int node = wi >> 4, w = wi & 15;
            bool b = mask_at(m1, mode, node * NIN + w * 32 + lane);
            unsigned bits = __ballot_sync(0xffffffffu, b);
            if (lane == 0) g_mT1[w * NHID + node] = bits;
        }
    } else {                               // mask2: words 0..4095
        const int mode = warp_detect(m2, lane);
        #pragma unroll
        for (int q = 0; q < 4; q++) {
            int wi = (gw - 1024) * 4 + q;
            int node = wi >> 3, w = wi & 7;
            bool b = mask_at(m2, mode, node * NHID + w * 32 + lane);
            unsigned bits = __ballot_sync(0xffffffffu, b);
            if (lane == 0) g_mT2[w * NIN + node] = bits;
        }
    }
}

// ---------------------------------------------------------------------------
// Warp bitonic sort of 32*R u32 keys, ascending. Element i = lane*R + r.
// ---------------------------------------------------------------------------
template<int R, int J>
__device__ __forceinline__ void inreg_pass(unsigned* key, int lane, int k) {
    if (2 * J > k) return;
    #pragma unroll
    for (int r = 0; r < R; r++) {
        if ((r & J) == 0) {
            bool asc = (((unsigned)(lane * R + r) & (unsigned)k) == 0);
            unsigned a = key[r], b = key[r + J];
            unsigned mn = a < b ? a : b;
            unsigned mx = a < b ? b : a;
            key[r]     = asc ? mn : mx;
            key[r + J] = asc ? mx : mn;
        }
    }
}

template<int R>
__device__ __forceinline__ void bitonic_sort_warp(unsigned* key) {
    const int lane = threadIdx.x & 31;
    const int N = 32 * R;
    for (int k = 2; k <= N; k <<= 1) {
        for (int m = (k >> 1) / R; m >= 1; m >>= 1) {
            #pragma unroll
            for (int r = 0; r < R; r++) {
                unsigned a = key[r];
                unsigned b = __shfl_xor_sync(0xffffffffu, a, m);
                bool asc   = (((unsigned)(lane * R + r) & (unsigned)k) == 0);
                bool lower = ((lane & m) == 0);
                unsigned mn = a < b ? a : b;
                unsigned mx = a < b ? b : a;
                key[r] = (lower == asc) ? mn : mx;
            }
        }
        if (R >= 16) inreg_pass<R, 8>(key, lane, k);
        if (R >= 8)  inreg_pass<R, 4>(key, lane, k);
        inreg_pass<R, 2>(key, lane, k);
        inreg_pass<R, 1>(key, lane, k);
    }
}

// ---------------------------------------------------------------------------
// Mega-fused kernel: BOTH layers for 4 batch rows per block (row-local!).
// Phase 1: warps 0-3 sort x rows | warps 4-7 stage masks+vals+sel.
// Phase 2: all threads walk layer 1 -> h in smem.
// Phase 3: warps 0-3 sort h rows. Phase 4: all threads walk layer 2 -> out.
// ---------------------------------------------------------------------------
struct SmemLayout {
    unsigned      keys1[4][NIN];        // 8 KB
    float         vals1[4][NIN];        // 8 KB
    unsigned      mask1[16 * NHID];     // 16 KB
    unsigned      mask2[8 * NIN];       // 16 KB
    float         h[4][NHID];           // 4 KB  (layer-2 values)
    unsigned      keys2[4][NHID];       // 4 KB
    unsigned char sel1[NHID];           // 256 B
    unsigned char sel2[NIN];            // 512 B
};

__global__ void __launch_bounds__(256) mega_kernel(const float* __restrict__ x,
                                                   float* __restrict__ out,
                                                   const float* __restrict__ logits1,
                                                   const float* __restrict__ u1,
                                                   const float* __restrict__ logits2,
                                                   const float* __restrict__ u2) {
    extern __shared__ __align__(16) char smem_raw[];
    SmemLayout& S = *reinterpret_cast<SmemLayout*>(smem_raw);

    const int tid  = threadIdx.x;
    const int warp = tid >> 5;
    const int lane = tid & 31;
    const int r0   = blockIdx.x * 4;

    // ---------------- Phase 1: sort x rows | stage everything ----------------
    if (warp < 4) {
        constexpr int R = NIN / 32;   // 16
        const float* src = x + (size_t)(r0 + warp) * NIN + lane * R;
        unsigned key[R];
        #pragma unroll
        for (int rr = 0; rr < R; rr += 4) {
            float4 v = *(const float4*)(src + rr);
            float vv[4] = {v.x, v.y, v.z, v.w};
            #pragma unroll
            for (int q = 0; q < 4; q++) {
                int c = lane * R + rr + q;
                key[rr + q] = (__float_as_uint(vv[q]) & ~(unsigned)(NIN - 1)) | (unsigned)c;
            }
        }
        bitonic_sort_warp<R>(key);
        #pragma unroll
        for (int rr = 0; rr < R; rr += 4) {
            uint4 o; o.x = key[rr]; o.y = key[rr + 1]; o.z = key[rr + 2]; o.w = key[rr + 3];
            *(uint4*)(&S.keys1[warp][lane * R + rr]) = o;
        }
    } else {
        const int t2 = tid - 128;   // 0..127
        // masks (both layers)
        const uint4* m14 = (const uint4*)g_mT1;
        const uint4* m24 = (const uint4*)g_mT2;
        uint4* sm14 = (uint4*)S.mask1;
        uint4* sm24 = (uint4*)S.mask2;
        #pragma unroll
        for (int i = t2; i < (16 * NHID) / 4; i += 128) sm14[i] = m14[i];
        #pragma unroll
        for (int i = t2; i < (8 * NIN) / 4; i += 128)  sm24[i] = m24[i];
        // exact x values for the 4 rows
        const float4* in4 = (const float4*)(x + (size_t)r0 * NIN);
        float4* sv4 = (float4*)&S.vals1[0][0];
        #pragma unroll
        for (int i = t2; i < (4 * NIN) / 4; i += 128) sv4[i] = in4[i];
        // sel for both layers
        #pragma unroll
        for (int n = t2; n < NHID; n += 128) {
            float z0 = logits1[2 * n]     + gumbel_f(u1[2 * n]);
            float z1 = logits1[2 * n + 1] + gumbel_f(u1[2 * n + 1]);
            S.sel1[n] = (z1 > z0) ? 1 : 0;
        }
        #pragma unroll
        for (int n = t2; n < NIN; n += 128) {
            float z0 = logits2[2 * n]     + gumbel_f(u2[2 * n]);
            float z1 = logits2[2 * n + 1] + gumbel_f(u2[2 * n + 1]);
            S.sel2[n] = (z1 > z0) ? 1 : 0;
        }
    }
    __syncthreads();

    // ---------------- Phase 2: layer-1 walk (node = tid), h -> smem ----------
    {
        const int node = tid;
        const int sel  = S.sel1[node];
        const unsigned posm = sel ? (unsigned)(NIN - 1) : 0u;
        const float idv = sel ? 0.0f : 1.0f;
        float v[4]; bool f[4];
        #pragma unroll
        for (int r = 0; r < 4; r++) { v[r] = idv; f[r] = false; }
        for (int t = 0; t < NIN; t++) {
            const unsigned p = (unsigned)t ^ posm;
            bool alldone = true;
            #pragma unroll
            for (int r = 0; r < 4; r++) {
                if (!f[r]) {
                    unsigned kk = S.keys1[r][p];
                    int idx = (int)(kk & (unsigned)(NIN - 1));
                    if ((S.mask1[(idx >> 5) * NHID + node] >> (idx & 31)) & 1u) {
                        v[r] = S.vals1[r][idx]; f[r] = true;
                    }
                }
                alldone &= f[r];
            }
            if (alldone) break;
        }
        #pragma unroll
        for (int r = 0; r < 4; r++) S.h[r][node] = fmaxf(v[r], 0.0f);
    }
    __syncthreads();

    // ---------------- Phase 3: sort h rows ----------------
    if (warp < 4) {
        constexpr int R = NHID / 32;   // 8
        unsigned key[R];
        #pragma unroll
        for (int rr = 0; rr < R; rr++) {
            int c = lane * R + rr;
            float hv = S.h[warp][c];
            key[rr] = (__float_as_uint(hv) & ~(unsigned)(NHID - 1)) | (unsigned)c;
        }
        bitonic_sort_warp<R>(key);
        #pragma unroll
        for (int rr = 0; rr < R; rr += 4) {
            uint4 o; o.x = key[rr]; o.y = key[rr + 1]; o.z = key[rr + 2]; o.w = key[rr + 3];
            *(uint4*)(&S.keys2[warp][lane * R + rr]) = o;
        }
    }
    __syncthreads();

    // ---------------- Phase 4: layer-2 walk (2 nodes/thread) -> global -------
    {
        unsigned posm[2]; float v[2][4]; bool f[2][4];
        #pragma unroll
        for (int np = 0; np < 2; np++) {
            const int node = np * 256 + tid;
            const int sel  = S.sel2[node];
            posm[np] = sel ? (unsigned)(NHID - 1) : 0u;
            const float idv = sel ? 0.0f : 1.0f;
            #pragma unroll
            for (int r = 0; r < 4; r++) { v[np][r] = idv; f[np][r] = false; }
        }
        for (int t = 0; t < NHID; t++) {
            bool alldone = true;
            #pragma unroll
            for (int np = 0; np < 2; np++) {
                const int node = np * 256 + tid;
                const unsigned p = (unsigned)t ^ posm[np];
                #pragma unroll
                for (int r = 0; r < 4; r++) {
                    if (!f[np][r]) {
                        unsigned kk = S.keys2[r][p];
                        int idx = (int)(kk & (unsigned)(NHID - 1));
                        if ((S.mask2[(idx >> 5) * NIN + node] >> (idx & 31)) & 1u) {
                            v[np][r] = S.h[r][idx]; f[np][r] = true;
                        }
                    }
                    alldone &= f[np][r];
                }
            }
            if (alldone) break;
        }
        #pragma unroll
        for (int np = 0; np < 2; np++) {
            const int node = np * 256 + tid;
            #pragma unroll
            for (int r = 0; r < 4; r++)
                out[(size_t)(r0 + r) * NIN + node] = fmaxf(v[np][r], 0.0f);
        }
    }
}

// ---------------------------------------------------------------------------
// kernel_launch: masks -> mega (both layers). Two launches.
// ---------------------------------------------------------------------------
extern "C" void kernel_launch(void* const* d_in, const int* in_sizes, int n_in,
                              void* d_out, int out_size) {
    const float* x       = (const float*)d_in[0];
    const float* logits1 = (const float*)d_in[1];
    const float* u1      = (const float*)d_in[2];
    const float* logits2 = (const float*)d_in[3];
    const float* u2      = (const float*)d_in[4];
    const void*  mask1   = d_in[5];
    const void*  mask2   = d_in[6];
    float* out = (float*)d_out;
    (void)in_sizes; (void)n_in; (void)out_size;

    const int smem = (int)sizeof(SmemLayout);
    cudaFuncSetAttribute(mega_kernel, cudaFuncAttributeMaxDynamicSharedMemorySize, smem);

    prep_masks_kernel<<<256, 256>>>(mask1, mask2);
    mega_kernel<<<BATCH / 4, 256, smem>>>(x, out, logits1, u1, logits2, u2);
}

// round 8
// speedup vs baseline: 1.3232x; 1.0783x over previous
#include <cuda_runtime.h>
#include <math.h>

#define BATCH 1024
#define NIN   512
#define NHID  256

// ---------------------------------------------------------------------------
// Device-global scratch (no allocation allowed anywhere).
// ---------------------------------------------------------------------------
__device__ unsigned g_mT1[16 * NHID];        // transposed bitmask [w][node], layer1
__device__ unsigned g_mT2[8 * NIN];          // transposed bitmask [w][node], layer2

// ---------------------------------------------------------------------------
// Gumbel hard-select: forward value is exactly one-hot of argmax(logits + g).
// ---------------------------------------------------------------------------
__device__ __forceinline__ float gumbel_f(float u) {
    u = fminf(fmaxf(u, 1e-10f), 1.0f);
    return -logf(-logf(u));
}

// Per-warp mask dtype detection: 2 lane-parallel loads + ballots.
__device__ __forceinline__ int warp_detect(const void* p, int lane) {
    const unsigned* pw = (const unsigned*)p;
    unsigned a = pw[lane], b = pw[lane + 32];
    bool i32 = (a <= 1u) && (b <= 1u);
    bool f32 = (a == 0u || a == 0x3F800000u) && (b == 0u || b == 0x3F800000u);
    i32 = __all_sync(0xffffffffu, i32);
    f32 = __all_sync(0xffffffffu, f32);
    return i32 ? 2 : (f32 ? 3 : 1);
}

__device__ __forceinline__ bool mask_at(const void* p, int mode, int e) {
    if (mode == 2) return ((const int*)p)[e] != 0;
    if (mode == 3) return ((const float*)p)[e] != 0.0f;
    return ((const unsigned char*)p)[e] != 0;
}

// Transposed bit-packed masks. One warp packs 4 words (coalesced + MLP).
__global__ void __launch_bounds__(256) prep_masks_kernel(const void* __restrict__ m1,
                                                         const void* __restrict__ m2) {
    const int gw   = (blockIdx.x * 256 + threadIdx.x) >> 5;   // 0..2047
    const int lane = threadIdx.x & 31;
    if (gw < 1024) {
        const int mode = warp_detect(m1, lane);
        #pragma unroll
        for (int q = 0; q < 4; q++) {
            int wi = gw * 4 + q;
            int node = wi >> 4, w = wi & 15;
            bool b = mask_at(m1, mode, node * NIN + w * 32 + lane);
            unsigned bits = __ballot_sync(0xffffffffu, b);
            if (lane == 0) g_mT1[w * NHID + node] = bits;
        }
    } else {
        const int mode = warp_detect(m2, lane);
        #pragma unroll
        for (int q = 0; q < 4; q++) {
            int wi = (gw - 1024) * 4 + q;
            int node = wi >> 3, w = wi & 7;
            bool b = mask_at(m2, mode, node * NHID + w * 32 + lane);
            unsigned bits = __ballot_sync(0xffffffffu, b);
            if (lane == 0) g_mT2[w * NIN + node] = bits;
        }
    }
}

// ---------------------------------------------------------------------------
// Warp bitonic sort of 32*R u32 keys, ascending. Element i = lane*R + r.
// ---------------------------------------------------------------------------
template<int R, int J>
__device__ __forceinline__ void inreg_pass(unsigned* key, int lane, int k) {
    if (2 * J > k) return;
    #pragma unroll
    for (int r = 0; r < R; r++) {
        if ((r & J) == 0) {
            bool asc = (((unsigned)(lane * R + r) & (unsigned)k) == 0);
            unsigned a = key[r], b = key[r + J];
            unsigned mn = a < b ? a : b;
            unsigned mx = a < b ? b : a;
            key[r]     = asc ? mn : mx;
            key[r + J] = asc ? mx : mn;
        }
    }
}

template<int R>
__device__ __forceinline__ void bitonic_sort_warp(unsigned* key) {
    const int lane = threadIdx.x & 31;
    const int N = 32 * R;
    for (int k = 2; k <= N; k <<= 1) {
        for (int m = (k >> 1) / R; m >= 1; m >>= 1) {
            #pragma unroll
            for (int r = 0; r < R; r++) {
                unsigned a = key[r];
                unsigned b = __shfl_xor_sync(0xffffffffu, a, m);
                bool asc   = (((unsigned)(lane * R + r) & (unsigned)k) == 0);
                bool lower = ((lane & m) == 0);
                unsigned mn = a < b ? a : b;
                unsigned mx = a < b ? b : a;
                key[r] = (lower == asc) ? mn : mx;
            }
        }
        if (R >= 16) inreg_pass<R, 8>(key, lane, k);
        if (R >= 8)  inreg_pass<R, 4>(key, lane, k);
        inreg_pass<R, 2>(key, lane, k);
        inreg_pass<R, 1>(key, lane, k);
    }
}

// Ascending bitonic MERGE of 32*R elements held by one warp (element = lane*R+r).
template<int R, int J>
__device__ __forceinline__ void inreg_merge_asc(unsigned* key) {
    #pragma unroll
    for (int r = 0; r < R; r++) {
        if ((r & J) == 0) {
            unsigned a = key[r], b = key[r + J];
            key[r]     = a < b ? a : b;
            key[r + J] = a < b ? b : a;
        }
    }
}

template<int R>
__device__ __forceinline__ void bitonic_merge_asc(unsigned* key) {
    const int lane = threadIdx.x & 31;
    #pragma unroll
    for (int m = 16; m >= 1; m >>= 1) {
        #pragma unroll
        for (int r = 0; r < R; r++) {
            unsigned a = key[r];
            unsigned b = __shfl_xor_sync(0xffffffffu, a, m);
            bool lower = ((lane & m) == 0);
            unsigned mn = a < b ? a : b;
            unsigned mx = a < b ? b : a;
            key[r] = lower ? mn : mx;
        }
    }
    if (R >= 8) inreg_merge_asc<R, 4>(key);
    if (R >= 4) inreg_merge_asc<R, 2>(key);
    inreg_merge_asc<R, 1>(key);
}

template<int R>
__device__ __forceinline__ void invert_keys(unsigned* key) {
    #pragma unroll
    for (int r = 0; r < R; r++) key[r] = ~key[r];
}

// ---------------------------------------------------------------------------
// Mega-fused kernel: BOTH layers for 2 batch rows per block, 512 blocks.
// Sorts are 2-warp cooperative: each warp sorts a 256/128-element half
// (ascending / descending via bitwise-NOT), one smem exchange implements the
// top bitonic-merge step, then each warp merges its half ascending.
// ---------------------------------------------------------------------------
struct SmemLayout {
    unsigned      keys1[2][NIN];        // 4 KB  (also the sort exchange buffer)
    float         vals1[2][NIN];        // 4 KB
    unsigned      mask1[16 * NHID];     // 16 KB
    unsigned      mask2[8 * NIN];       // 16 KB
    float         h[2][NHID];           // 2 KB
    unsigned      keys2[2][NHID];       // 2 KB
    unsigned char sel1[NHID];
    unsigned char sel2[NIN];
};

__global__ void __launch_bounds__(256) mega_kernel(const float* __restrict__ x,
                                                   float* __restrict__ out,
                                                   const float* __restrict__ logits1,
                                                   const float* __restrict__ u1,
                                                   const float* __restrict__ logits2,
                                                   const float* __restrict__ u2) {
    __shared__ SmemLayout S;

    const int tid  = threadIdx.x;
    const int warp = tid >> 5;
    const int lane = tid & 31;
    const int r0   = blockIdx.x * 2;

    // ============ Phase 1: local half-sorts (warps 0-3) | staging (4-7) ======
    unsigned key[8];                      // persists across the exchange barriers
    const int pr   = warp >> 1;           // pair row (0..1) for sort warps
    const int half = warp & 1;            // 0 = low half (asc), 1 = high (desc)

    if (warp < 4) {
        // load my 256-element half of x row pr (coalesced 2×float4/lane)
        const float* src = x + (size_t)(r0 + pr) * NIN + half * 256 + lane * 8;
        #pragma unroll
        for (int rr = 0; rr < 8; rr += 4) {
            float4 v = *(const float4*)(src + rr);
            float vv[4] = {v.x, v.y, v.z, v.w};
            #pragma unroll
            for (int q = 0; q < 4; q++) {
                int c = half * 256 + lane * 8 + rr + q;     // global element idx
                key[rr + q] = (__float_as_uint(vv[q]) & ~(unsigned)(NIN - 1)) | (unsigned)c;
            }
        }
        if (half) invert_keys<8>(key);
        bitonic_sort_warp<8>(key);        // asc on (possibly inverted) keys
        if (half) invert_keys<8>(key);    // now desc
        #pragma unroll
        for (int rr = 0; rr < 8; rr++)
            S.keys1[pr][half * 256 + lane * 8 + rr] = key[rr];
    } else {
        const int t2 = tid - 128;   // 0..127
        const uint4* m14 = (const uint4*)g_mT1;
        const uint4* m24 = (const uint4*)g_mT2;
        uint4* sm14 = (uint4*)S.mask1;
        uint4* sm24 = (uint4*)S.mask2;
        #pragma unroll
        for (int i = t2; i < (16 * NHID) / 4; i += 128) sm14[i] = m14[i];
        #pragma unroll
        for (int i = t2; i < (8 * NIN) / 4; i += 128)  sm24[i] = m24[i];
        const float4* in4 = (const float4*)(x + (size_t)r0 * NIN);
        float4* sv4 = (float4*)&S.vals1[0][0];
        #pragma unroll
        for (int i = t2; i < (2 * NIN) / 4; i += 128) sv4[i] = in4[i];
        #pragma unroll
        for (int n = t2; n < NHID; n += 128) {
            float z0 = logits1[2 * n]     + gumbel_f(u1[2 * n]);
            float z1 = logits1[2 * n + 1] + gumbel_f(u1[2 * n + 1]);
            S.sel1[n] = (z1 > z0) ? 1 : 0;
        }
        #pragma unroll
        for (int n = t2; n < NIN; n += 128) {
            float z0 = logits2[2 * n]     + gumbel_f(u2[2 * n]);
            float z1 = logits2[2 * n + 1] + gumbel_f(u2[2 * n + 1]);
            S.sel2[n] = (z1 > z0) ? 1 : 0;
        }
    }
    __syncthreads();

    // ============ Phase 1b: cross-warp merge step + warp-local merge =========
    if (warp < 4) {
        #pragma unroll
        for (int rr = 0; rr < 8; rr++) {
            unsigned p = S.keys1[pr][(half ^ 1) * 256 + lane * 8 + rr];
            unsigned a = key[rr];
            key[rr] = half ? (a > p ? a : p) : (a < p ? a : p);
        }
        bitonic_merge_asc<8>(key);
    }
    __syncthreads();   // partner reads done before overwrite
    if (warp < 4) {
        #pragma unroll
        for (int rr = 0; rr < 8; rr++)
            S.keys1[pr][half * 256 + lane * 8 + rr] = key[rr];
    }
    __syncthreads();

    // ============ Phase 2: layer-1 walk (node = tid, 2 row-chains) ===========
    {
        const int node = tid;
        const int sel  = S.sel1[node];
        const unsigned posm = sel ? (unsigned)(NIN - 1) : 0u;
        const float idv = sel ? 0.0f : 1.0f;
        float v[2]; bool f[2];
        #pragma unroll
        for (int r = 0; r < 2; r++) { v[r] = idv; f[r] = false; }
        for (int t = 0; t < NIN; t++) {
            const unsigned p = (unsigned)t ^ posm;
            bool alldone = true;
            #pragma unroll
            for (int r = 0; r < 2; r++) {
                if (!f[r]) {
                    unsigned kk = S.keys1[r][p];
                    int idx = (int)(kk & (unsigned)(NIN - 1));
                    if ((S.mask1[(idx >> 5) * NHID + node] >> (idx & 31)) & 1u) {
                        v[r] = S.vals1[r][idx]; f[r] = true;
                    }
                }
                alldone &= f[r];
            }
            if (alldone) break;
        }
        #pragma unroll
        for (int r = 0; r < 2; r++) S.h[r][node] = fmaxf(v[r], 0.0f);
    }
    __syncthreads();

    // ============ Phase 3: cooperative sort of the 2 h rows (warps 0-3) ======
    if (warp < 4) {
        #pragma unroll
        for (int rr = 0; rr < 4; rr++) {
            int c = half * 128 + lane * 4 + rr;
            float hv = S.h[pr][c];
            key[rr] = (__float_as_uint(hv) & ~(unsigned)(NHID - 1)) | (unsigned)c;
        }
        if (half) invert_keys<4>(key);
        bitonic_sort_warp<4>(key);
        if (half) invert_keys<4>(key);
        #pragma unroll
        for (int rr = 0; rr < 4; rr++)
            S.keys2[pr][half * 128 + lane * 4 + rr] = key[rr];
    }
    __syncthreads();
    if (warp < 4) {
        #pragma unroll
        for (int rr = 0; rr < 4; rr++) {
            unsigned p = S.keys2[pr][(half ^ 1) * 128 + lane * 4 + rr];
            unsigned a = key[rr];
            key[rr] = half ? (a > p ? a : p) : (a < p ? a : p);
        }
        bitonic_merge_asc<4>(key);
    }
    __syncthreads();
    if (warp < 4) {
        #pragma unroll
        for (int rr = 0; rr < 4; rr++)
            S.keys2[pr][half * 128 + lane * 4 + rr] = key[rr];
    }
    __syncthreads();

    // ============ Phase 4: layer-2 walk (2 nodes × 2 rows per thread) ========
    {
        unsigned posm[2]; float v[2][2]; bool f[2][2];
        #pragma unroll
        for (int np = 0; np < 2; np++) {
            const int node = np * 256 + tid;
            const int sel  = S.sel2[node];
            posm[np] = sel ? (unsigned)(NHID - 1) : 0u;
            const float idv = sel ? 0.0f : 1.0f;
            #pragma unroll
            for (int r = 0; r < 2; r++) { v[np][r] = idv; f[np][r] = false; }
        }
        for (int t = 0; t < NHID; t++) {
            bool alldone = true;
            #pragma unroll
            for (int np = 0; np < 2; np++) {
                const int node = np * 256 + tid;
                const unsigned p = (unsigned)t ^ posm[np];
                #pragma unroll
                for (int r = 0; r < 2; r++) {
                    if (!f[np][r]) {
                        unsigned kk = S.keys2[r][p];
                        int idx = (int)(kk & (unsigned)(NHID - 1));
                        if ((S.mask2[(idx >> 5) * NIN + node] >> (idx & 31)) & 1u) {
                            v[np][r] = S.h[r][idx]; f[np][r] = true;
                        }
                    }
                    alldone &= f[np][r];
                }
            }
            if (alldone) break;
        }
        #pragma unroll
        for (int np = 0; np < 2; np++) {
            const int node = np * 256 + tid;
            #pragma unroll
            for (int r = 0; r < 2; r++)
                out[(size_t)(r0 + r) * NIN + node] = fmaxf(v[np][r], 0.0f);
        }
    }
}

// ---------------------------------------------------------------------------
// kernel_launch: masks -> mega (both layers). Two launches.
// ---------------------------------------------------------------------------
extern "C" void kernel_launch(void* const* d_in, const int* in_sizes, int n_in,
                              void* d_out, int out_size) {
    const float* x       = (const float*)d_in[0];
    const float* logits1 = (const float*)d_in[1];
    const float* u1      = (const float*)d_in[2];
    const float* logits2 = (const float*)d_in[3];
    const float* u2      = (const float*)d_in[4];
    const void*  mask1   = d_in[5];
    const void*  mask2   = d_in[6];
    float* out = (float*)d_out;
    (void)in_sizes; (void)n_in; (void)out_size;

    prep_masks_kernel<<<256, 256>>>(mask1, mask2);
    mega_kernel<<<BATCH / 2, 256>>>(x, out, logits1, u1, logits2, u2);
}